// round 10
// baseline (speedup 1.0000x reference)
#include <cuda_runtime.h>
#include <cstdint>

#define Nn 100000
#define Rr 8
#define Dd 64
#define Tt 16
#define Pp 32
#define Ee 1600000
#define NR (Nn*Rr)          // 800000 segments
#define KTOT 576            // 8*64 (relations) + 64 (root)
#define KS   512
#define TILE 128
#define NTILES ((Nn + TILE - 1) / TILE)   // 782
#define KC    64            // K-chunk = one relation (or root)
#define NCHK  9             // 8 relations + root
#define APITCH 68           // A smem pitch: 68%32=4 -> conflict-free frags
#define WPITCH 580          // Wt smem pitch: 580%32=4 -> conflict-free frags
#define SCAN_BLKS ((NR + 1023) / 1024)    // 782

// Scratch (device globals: no allocations allowed)
__device__ float g_h[(size_t)Nn*Dd];
__device__ float g_h2[(size_t)Nn*Dd];
__device__ int   g_cnt[NR];
__device__ int   g_off[NR + 1];           // CSR offsets
__device__ int   g_cur[NR];               // fill cursors
__device__ int   g_esrc[Ee];              // src ids sorted by (dst,rel)
__device__ int   g_bsum[SCAN_BLKS];
__device__ int   g_bbase[SCAN_BLKS];

// ---------------------------------------------------------------------------
__global__ void zero_k() {
    int i = blockIdx.x*blockDim.x + threadIdx.x;
    if (i < NR) { g_cnt[i] = 0; g_cur[i] = 0; }
}

__global__ void count_k(const int* __restrict__ dst, const int* __restrict__ et) {
    int e = blockIdx.x*blockDim.x + threadIdx.x;
    if (e < Ee) atomicAdd(&g_cnt[dst[e]*Rr + et[e]], 1);
}

// ---------------------------------------------------------------------------
// exclusive scan of g_cnt -> g_off  (3 kernels, 1024 elems per block)
// ---------------------------------------------------------------------------
__device__ __forceinline__ int blk_excl_scan_1024(const int* in, int* out,
                                                  int base, int nmax) {
    __shared__ int swarp[8];
    const int t = threadIdx.x, lane = t & 31, w = t >> 5;
    int idx = base + t*4;
    int a0 = (idx+0 < nmax) ? in[idx+0] : 0;
    int a1 = (idx+1 < nmax) ? in[idx+1] : 0;
    int a2 = (idx+2 < nmax) ? in[idx+2] : 0;
    int a3 = (idx+3 < nmax) ? in[idx+3] : 0;
    int tsum = a0 + a1 + a2 + a3;
    int v = tsum;
    #pragma unroll
    for (int d = 1; d < 32; d <<= 1) {
        int u = __shfl_up_sync(0xffffffffu, v, d);
        if (lane >= d) v += u;
    }
    if (lane == 31) swarp[w] = v;
    __syncthreads();
    if (t == 0) { int r = 0; for (int i = 0; i < 8; i++) { int q = swarp[i]; swarp[i] = r; r += q; } }
    __syncthreads();
    int e0 = swarp[w] + (v - tsum);
    if (idx+0 < nmax) out[idx+0] = e0;
    if (idx+1 < nmax) out[idx+1] = e0 + a0;
    if (idx+2 < nmax) out[idx+2] = e0 + a0 + a1;
    if (idx+3 < nmax) out[idx+3] = e0 + a0 + a1 + a2;
    return swarp[7] + ((w == 7) ? v : 0);   // valid for t==255
}

__global__ void scan1_k() {
    int total = blk_excl_scan_1024(g_cnt, g_off, blockIdx.x*1024, NR);
    if (threadIdx.x == 255) g_bsum[blockIdx.x] = total;
}
__global__ void scan2_k() {
    blk_excl_scan_1024(g_bsum, g_bbase, 0, SCAN_BLKS);
}
__global__ void scan3_k() {
    int i = blockIdx.x*blockDim.x + threadIdx.x;
    if (i < NR) g_off[i] += g_bbase[i >> 10];
    if (i == 0) g_off[NR] = Ee;
}

__global__ void fill_k(const int* __restrict__ src, const int* __restrict__ dst,
                       const int* __restrict__ et) {
    int e = blockIdx.x*blockDim.x + threadIdx.x;
    if (e < Ee) {
        int seg = dst[e]*Rr + et[e];
        int pos = g_off[seg] + atomicAdd(&g_cur[seg], 1);
        if (pos >= 0 && pos < Ee) g_esrc[pos] = src[e];
    }
}

// ---------------------------------------------------------------------------
// h0 = node_emb[x] + type_emb[node_type] + MLP(node_properties)
// ---------------------------------------------------------------------------
__global__ void mlp_k(const int* __restrict__ x, const int* __restrict__ ntype,
                      const float* __restrict__ props, const float* __restrict__ nemb,
                      const float* __restrict__ temb,
                      const float* __restrict__ w1, const float* __restrict__ b1,
                      const float* __restrict__ w2, const float* __restrict__ b2) {
    __shared__ float sw1[Pp*Dd];
    __shared__ float sw2[Dd*Dd];
    __shared__ float sb1[Dd], sb2[Dd];
    __shared__ float shid[4][Dd];
    for (int i = threadIdx.x; i < Pp*Dd; i += 256) sw1[i] = w1[i];
    for (int i = threadIdx.x; i < Dd*Dd; i += 256) sw2[i] = w2[i];
    if (threadIdx.x < Dd) { sb1[threadIdx.x] = b1[threadIdx.x]; sb2[threadIdx.x] = b2[threadIdx.x]; }
    __syncthreads();
    const int g = threadIdx.x >> 6, j = threadIdx.x & 63;
    for (int n0 = blockIdx.x*4; n0 < Nn; n0 += gridDim.x*4) {
        int n = n0 + g;
        float hj = 0.f;
        if (n < Nn) {
            hj = sb1[j];
            const float* pr = props + (size_t)n*Pp;
            #pragma unroll
            for (int p = 0; p < Pp; p++) hj = fmaf(__ldg(pr+p), sw1[p*Dd+j], hj);
            hj = fmaxf(hj, 0.f);
        }
        shid[g][j] = hj;
        __syncthreads();
        if (n < Nn) {
            float o = sb2[j];
            #pragma unroll
            for (int k = 0; k < Dd; k++) o = fmaf(shid[g][k], sw2[k*Dd+j], o);
            o += nemb[(size_t)x[n]*Dd + j] + temb[(size_t)ntype[n]*Dd + j];
            g_h[(size_t)n*Dd + j] = o;
        }
        __syncthreads();
    }
}

// ---------------------------------------------------------------------------
// FUSED transform: aggregation + tf32 GEMM in one persistent kernel.
//   out[n] = h[n] + relu([Sbar[n] | h[n]] @ [W;Wroot] + b)
// 512 threads: warps 0-7 = MMA consumers (4m x 2n, 128x64 tile),
//              warps 8-15 = producers (gather-mean h rows per (node,rel) seg
//              straight into SMEM A-stages; K-chunk = 1 relation = 64 floats).
// 2-stage ring, named-barrier full/empty handoff. g_S eliminated.
// ---------------------------------------------------------------------------
__device__ __forceinline__ uint32_t f2tf32(float x) {
    uint32_t r;
    asm("cvt.rna.tf32.f32 %0, %1;" : "=r"(r) : "f"(x));
    return r;
}
__device__ __forceinline__ void mma_tf32(float c[4], uint32_t a0, uint32_t a1,
                                         uint32_t a2, uint32_t a3,
                                         uint32_t b0, uint32_t b1) {
    asm volatile("mma.sync.aligned.m16n8k8.row.col.f32.tf32.tf32.f32 "
                 "{%0,%1,%2,%3}, {%4,%5,%6,%7}, {%8,%9}, {%0,%1,%2,%3};"
                 : "+f"(c[0]), "+f"(c[1]), "+f"(c[2]), "+f"(c[3])
                 : "r"(a0), "r"(a1), "r"(a2), "r"(a3), "r"(b0), "r"(b1));
}
#define BAR_SYNC(id)   asm volatile("bar.sync %0, %1;"   :: "r"(id), "r"(512) : "memory")
#define BAR_ARRIVE(id) asm volatile("bar.arrive %0, %1;" :: "r"(id), "r"(512) : "memory")
// barrier ids: empty(st) = 1+st, full(st) = 3+st

__global__ void __launch_bounds__(512, 1) transform_k(
    const float* __restrict__ W, const float* __restrict__ Wroot,
    const float* __restrict__ b, const float* __restrict__ hin,
    float* __restrict__ out) {
    extern __shared__ float sm[];
    uint32_t* sWt = (uint32_t*)sm;            // [64][WPITCH] tf32, transposed
    float*    sA  = sm + 64*WPITCH;           // 2 stages x [128][APITCH]
    const int tid  = threadIdx.x;
    const int lane = tid & 31;
    const int wid  = tid >> 5;

    // Wt[n][k] = tf32(W[k][n]); k=r*64+i for W (R,Din,Dout); Wroot at k>=512
    for (int idx = tid; idx < KTOT*Dd; idx += 512) {
        int k = idx >> 6, n = idx & 63;
        float v = (k < KS) ? W[(size_t)k*Dd + n] : Wroot[(size_t)(k-KS)*Dd + n];
        sWt[n*WPITCH + k] = f2tf32(v);
    }
    __syncthreads();

    int cc = 0;                                // running chunk counter (both roles)

    if (wid >= 8) {
        // ================= PRODUCERS (warps 8-15) =================
        const int pw = wid - 8;                // 0..7 -> rows pw*16 .. pw*16+15
        for (int tile = blockIdx.x; tile < NTILES; tile += gridDim.x) {
            const int node0 = tile * TILE;
            for (int kc = 0; kc < NCHK; kc++, cc++) {
                const int st = cc & 1;
                if (cc >= 2) BAR_SYNC(1 + st);           // wait empty
                float* sAst = sA + st*TILE*APITCH;
                if (kc < 8) {
                    const int r = kc;                     // relation
                    #pragma unroll
                    for (int q = 0; q < 4; q++) {
                        int nd0 = pw*16 + q*4;
                        int beg[4], len[4];
                        #pragma unroll
                        for (int j = 0; j < 4; j++) {
                            int n = node0 + nd0 + j;
                            if (n < Nn) {
                                int sg = n*Rr + r;
                                beg[j] = __ldg(g_off + sg);
                                len[j] = __ldg(g_off + sg + 1) - beg[j];
                            } else { beg[j] = 0; len[j] = 0; }
                        }
                        float2 acc[4];
                        #pragma unroll
                        for (int j = 0; j < 4; j++) acc[j] = make_float2(0.f, 0.f);
                        int maxlen = max(max(len[0], len[1]), max(len[2], len[3]));
                        for (int t = 0; t < maxlen; t++) {
                            #pragma unroll
                            for (int j = 0; j < 4; j++) {
                                if (t < len[j]) {
                                    int s = __ldg(g_esrc + beg[j] + t);
                                    float2 v = *(const float2*)(hin + (size_t)s*Dd + lane*2);
                                    acc[j].x += v.x; acc[j].y += v.y;
                                }
                            }
                        }
                        #pragma unroll
                        for (int j = 0; j < 4; j++) {
                            float iv = 1.0f / (float)max(len[j], 1);
                            *(float2*)(sAst + (nd0 + j)*APITCH + lane*2) =
                                make_float2(acc[j].x*iv, acc[j].y*iv);
                        }
                    }
                } else {
                    // root chunk: A[nd] = h[node0+nd]
                    #pragma unroll
                    for (int i = 0; i < 16; i++) {
                        int nd = pw*16 + i;
                        int n  = node0 + nd;
                        float2 v = make_float2(0.f, 0.f);
                        if (n < Nn) v = *(const float2*)(hin + (size_t)n*Dd + lane*2);
                        *(float2*)(sAst + nd*APITCH + lane*2) = v;
                    }
                }
                __threadfence_block();
                BAR_ARRIVE(3 + st);                      // signal full
            }
        }
    } else {
        // ================= CONSUMERS (warps 0-7) =================
        const int g   = lane >> 2;
        const int tig = lane & 3;
        const int wm  = wid & 3;
        const int wn  = wid >> 2;
        for (int tile = blockIdx.x; tile < NTILES; tile += gridDim.x) {
            const int node0 = tile * TILE;
            float acc[2][4][4];
            #pragma unroll
            for (int mf = 0; mf < 2; mf++)
                #pragma unroll
                for (int nf = 0; nf < 4; nf++)
                    { acc[mf][nf][0]=0.f; acc[mf][nf][1]=0.f; acc[mf][nf][2]=0.f; acc[mf][nf][3]=0.f; }

            for (int kc = 0; kc < NCHK; kc++, cc++) {
                const int st = cc & 1;
                BAR_SYNC(3 + st);                        // wait full
                const float* aS = sA + st*TILE*APITCH;
                #pragma unroll
                for (int ks = 0; ks < KC/8; ks++) {
                    const int kl = ks*8;
                    const int kg = kc*KC + kl;
                    #pragma unroll
                    for (int mf = 0; mf < 2; mf++) {
                        const float* ap = aS + (wm*32 + mf*16)*APITCH + kl;
                        uint32_t a0 = f2tf32(ap[ g     *APITCH + tig    ]);
                        uint32_t a1 = f2tf32(ap[(g + 8)*APITCH + tig    ]);
                        uint32_t a2 = f2tf32(ap[ g     *APITCH + tig + 4]);
                        uint32_t a3 = f2tf32(ap[(g + 8)*APITCH + tig + 4]);
                        #pragma unroll
                        for (int nf = 0; nf < 4; nf++) {
                            const uint32_t* bp = sWt + (wn*32 + nf*8 + g)*WPITCH + kg + tig;
                            mma_tf32(acc[mf][nf], a0, a1, a2, a3, bp[0], bp[4]);
                        }
                    }
                }
                BAR_ARRIVE(1 + st);                      // signal empty
            }

            // epilogue: out = h + relu(acc + bias)  (no sA access)
            #pragma unroll
            for (int mf = 0; mf < 2; mf++) {
                #pragma unroll
                for (int nf = 0; nf < 4; nf++) {
                    int col = wn*32 + nf*8 + tig*2;
                    float2 bv = *(const float2*)(b + col);
                    #pragma unroll
                    for (int half = 0; half < 2; half++) {
                        int r = node0 + wm*32 + mf*16 + g + half*8;
                        if (r < Nn) {
                            float2 hv = *(const float2*)(hin + (size_t)r*Dd + col);
                            float2 o;
                            o.x = hv.x + fmaxf(acc[mf][nf][half*2 + 0] + bv.x, 0.f);
                            o.y = hv.y + fmaxf(acc[mf][nf][half*2 + 1] + bv.y, 0.f);
                            *(float2*)(out + (size_t)r*Dd + col) = o;
                        }
                    }
                }
            }
        }
    }
}

// ---------------------------------------------------------------------------
extern "C" void kernel_launch(void* const* d_in, const int* in_sizes, int n_in,
                              void* d_out, int out_size) {
    const int*   x     = (const int*)d_in[0];
    const int*   eidx  = (const int*)d_in[1];
    const int*   et    = (const int*)d_in[2];
    const int*   ntype = (const int*)d_in[3];
    const float* props = (const float*)d_in[4];
    const float* nemb  = (const float*)d_in[5];
    const float* temb  = (const float*)d_in[6];
    const float* pw1   = (const float*)d_in[7];
    const float* pb1   = (const float*)d_in[8];
    const float* pw2   = (const float*)d_in[9];
    const float* pb2   = (const float*)d_in[10];
    const float* W1    = (const float*)d_in[11];
    const float* Wr1   = (const float*)d_in[12];
    const float* b1    = (const float*)d_in[13];
    const float* W2    = (const float*)d_in[14];
    const float* Wr2   = (const float*)d_in[15];
    const float* b2    = (const float*)d_in[16];
    float* out = (float*)d_out;
    const int* src = eidx;
    const int* dst = eidx + Ee;

    void *ph, *ph2;
    cudaGetSymbolAddress(&ph,  g_h);
    cudaGetSymbolAddress(&ph2, g_h2);
    float* h  = (float*)ph;
    float* h2 = (float*)ph2;

    size_t smem = (size_t)(64*WPITCH + 2*TILE*APITCH) * sizeof(float);   // 218112 B
    cudaFuncSetAttribute(transform_k, cudaFuncAttributeMaxDynamicSharedMemorySize, (int)smem);

    // ---- CSR build ----
    zero_k<<<(NR+255)/256, 256>>>();
    count_k<<<(Ee+255)/256, 256>>>(dst, et);
    scan1_k<<<SCAN_BLKS, 256>>>();
    scan2_k<<<1, 256>>>();
    scan3_k<<<(NR+255)/256, 256>>>();
    fill_k<<<(Ee+255)/256, 256>>>(src, dst, et);
    mlp_k<<<1536, 256>>>(x, ntype, props, nemb, temb, pw1, pb1, pw2, pb2);

    // fused layers (aggregation + GEMM, no g_S round-trip)
    transform_k<<<148, 512, smem>>>(W1, Wr1, b1, h, h2);
    transform_k<<<148, 512, smem>>>(W2, Wr2, b2, h2, out);
}

// round 12
// speedup vs baseline: 1.8583x; 1.8583x over previous
#include <cuda_runtime.h>
#include <cuda_fp16.h>
#include <cstring>
#include <cstdint>

#define Nn 100000
#define Rr 8
#define Dd 64
#define Tt 16
#define Pp 32
#define Ee 1600000
#define NR (Nn*Rr)          // 800000 segments
#define KTOT 576            // 8*64 (relations) + 64 (root)
#define KS   512            // S halves per node
#define TILE 128
#define NTILES ((Nn + TILE - 1) / TILE)   // 782
#define KC    64            // K-chunk width (halves)
#define NCHK  9             // 8 S chunks + 1 root chunk
#define NSTG  4             // pipeline stages
#define APITCH 36           // A smem pitch (uint32 words/row): 36%32=4 -> conflict-free
#define WPITCH 292          // Wt smem pitch (uint32 words/n-row): 292%32=4 -> conflict-free
#define SCAN_BLKS ((NR + 1023) / 1024)    // 782

// Scratch (device globals: no allocations allowed)
__device__ __half g_Sh[(size_t)Nn*KS];    // 102.4 MB per-(node,rel) mean sums, fp16
__device__ float  g_h[(size_t)Nn*Dd];     // fp32 features (residual/gather)
__device__ float  g_h2[(size_t)Nn*Dd];
__device__ __half g_hh[(size_t)Nn*Dd];    // fp16 mirror for A-feed (layer 1)
__device__ __half g_hh2[(size_t)Nn*Dd];   // fp16 mirror (layer 2)
__device__ int   g_cnt[NR];
__device__ int   g_off[NR + 1];           // CSR offsets
__device__ int   g_cur[NR];               // fill cursors
__device__ int   g_esrc[Ee];              // src ids sorted by (dst,rel)
__device__ int   g_bsum[SCAN_BLKS];
__device__ int   g_bbase[SCAN_BLKS];

__device__ __forceinline__ uint32_t h2_bits(__half2 v) {
    uint32_t r;
    memcpy(&r, &v, 4);
    return r;
}

// ---------------------------------------------------------------------------
__global__ void zero_k() {
    int i = blockIdx.x*blockDim.x + threadIdx.x;
    if (i < NR) { g_cnt[i] = 0; g_cur[i] = 0; }
}

__global__ void count_k(const int* __restrict__ dst, const int* __restrict__ et) {
    int e = blockIdx.x*blockDim.x + threadIdx.x;
    if (e < Ee) atomicAdd(&g_cnt[dst[e]*Rr + et[e]], 1);
}

// ---------------------------------------------------------------------------
// exclusive scan of g_cnt -> g_off  (3 kernels, 1024 elems per block)
// ---------------------------------------------------------------------------
__device__ __forceinline__ int blk_excl_scan_1024(const int* in, int* out,
                                                  int base, int nmax) {
    __shared__ int swarp[8];
    const int t = threadIdx.x, lane = t & 31, w = t >> 5;
    int idx = base + t*4;
    int a0 = (idx+0 < nmax) ? in[idx+0] : 0;
    int a1 = (idx+1 < nmax) ? in[idx+1] : 0;
    int a2 = (idx+2 < nmax) ? in[idx+2] : 0;
    int a3 = (idx+3 < nmax) ? in[idx+3] : 0;
    int tsum = a0 + a1 + a2 + a3;
    int v = tsum;
    #pragma unroll
    for (int d = 1; d < 32; d <<= 1) {
        int u = __shfl_up_sync(0xffffffffu, v, d);
        if (lane >= d) v += u;
    }
    if (lane == 31) swarp[w] = v;
    __syncthreads();
    if (t == 0) { int r = 0; for (int i = 0; i < 8; i++) { int q = swarp[i]; swarp[i] = r; r += q; } }
    __syncthreads();
    int e0 = swarp[w] + (v - tsum);
    if (idx+0 < nmax) out[idx+0] = e0;
    if (idx+1 < nmax) out[idx+1] = e0 + a0;
    if (idx+2 < nmax) out[idx+2] = e0 + a0 + a1;
    if (idx+3 < nmax) out[idx+3] = e0 + a0 + a1 + a2;
    return swarp[7] + ((w == 7) ? v : 0);   // valid for t==255
}

__global__ void scan1_k() {
    int total = blk_excl_scan_1024(g_cnt, g_off, blockIdx.x*1024, NR);
    if (threadIdx.x == 255) g_bsum[blockIdx.x] = total;
}
__global__ void scan2_k() {
    blk_excl_scan_1024(g_bsum, g_bbase, 0, SCAN_BLKS);
}
__global__ void scan3_k() {
    int i = blockIdx.x*blockDim.x + threadIdx.x;
    if (i < NR) g_off[i] += g_bbase[i >> 10];
    if (i == 0) g_off[NR] = Ee;
}

__global__ void fill_k(const int* __restrict__ src, const int* __restrict__ dst,
                       const int* __restrict__ et) {
    int e = blockIdx.x*blockDim.x + threadIdx.x;
    if (e < Ee) {
        int seg = dst[e]*Rr + et[e];
        int pos = g_off[seg] + atomicAdd(&g_cur[seg], 1);
        if (pos >= 0 && pos < Ee) g_esrc[pos] = src[e];
    }
}

// ---------------------------------------------------------------------------
// h0 = node_emb[x] + type_emb[node_type] + MLP(node_properties); fp32 + fp16 mirror
// ---------------------------------------------------------------------------
__global__ void mlp_k(const int* __restrict__ x, const int* __restrict__ ntype,
                      const float* __restrict__ props, const float* __restrict__ nemb,
                      const float* __restrict__ temb,
                      const float* __restrict__ w1, const float* __restrict__ b1,
                      const float* __restrict__ w2, const float* __restrict__ b2) {
    __shared__ float sw1[Pp*Dd];
    __shared__ float sw2[Dd*Dd];
    __shared__ float sb1[Dd], sb2[Dd];
    __shared__ float shid[4][Dd];
    for (int i = threadIdx.x; i < Pp*Dd; i += 256) sw1[i] = w1[i];
    for (int i = threadIdx.x; i < Dd*Dd; i += 256) sw2[i] = w2[i];
    if (threadIdx.x < Dd) { sb1[threadIdx.x] = b1[threadIdx.x]; sb2[threadIdx.x] = b2[threadIdx.x]; }
    __syncthreads();
    const int g = threadIdx.x >> 6, j = threadIdx.x & 63;
    for (int n0 = blockIdx.x*4; n0 < Nn; n0 += gridDim.x*4) {
        int n = n0 + g;
        float hj = 0.f;
        if (n < Nn) {
            hj = sb1[j];
            const float* pr = props + (size_t)n*Pp;
            #pragma unroll
            for (int p = 0; p < Pp; p++) hj = fmaf(__ldg(pr+p), sw1[p*Dd+j], hj);
            hj = fmaxf(hj, 0.f);
        }
        shid[g][j] = hj;
        __syncthreads();
        if (n < Nn) {
            float o = sb2[j];
            #pragma unroll
            for (int k = 0; k < Dd; k++) o = fmaf(shid[g][k], sw2[k*Dd+j], o);
            o += nemb[(size_t)x[n]*Dd + j] + temb[(size_t)ntype[n]*Dd + j];
            g_h[(size_t)n*Dd + j]  = o;
            g_hh[(size_t)n*Dd + j] = __float2half_rn(o);
        }
        __syncthreads();
    }
}

// ---------------------------------------------------------------------------
// segmented mean: Sh[seg,:] = (1/len) * sum_{e in seg} h[esrc[e], :]  (fp16 out)
// warp per segment; fp32 accumulate; no atomics, no memset, writes once.
// ---------------------------------------------------------------------------
__global__ void __launch_bounds__(256) seg_sum_k(const float* __restrict__ hin) {
    const int lane = threadIdx.x & 31;
    const int warp = (blockIdx.x*256 + threadIdx.x) >> 5;
    const int nwarp = (gridDim.x*256) >> 5;
    for (int seg = warp; seg < NR; seg += nwarp) {
        int beg = __ldg(g_off + seg), end = __ldg(g_off + seg + 1);
        float2 acc = make_float2(0.f, 0.f);
        for (int e = beg; e < end; e++) {
            int s = __ldg(g_esrc + e);
            float2 v = *(const float2*)(hin + (size_t)s*Dd + lane*2);
            acc.x += v.x; acc.y += v.y;
        }
        float iv = 1.0f / (float)max(end - beg, 1);
        ((__half2*)(g_Sh + (size_t)seg*Dd))[lane] =
            __floats2half2_rn(acc.x*iv, acc.y*iv);
    }
}

// ---------------------------------------------------------------------------
// fp16 tensor-core transform (m16n8k16), deep cp.async pipeline:
//   out[n] = h[n] + relu([Sbar[n] | h[n]] @ [W;Wroot] + b)
// Persistent grid=148. Wt (fp16, transposed, 73KB) in SMEM once per block.
// 128-node tiles, 64-half K-chunks (128B/row), 4-stage ring, wait_group<2>.
// 8 warps = 4(m) x 2(n); warp tile 32x32. B frags hoisted across mf.
// ---------------------------------------------------------------------------
__device__ __forceinline__ void mma_f16(float c[4], uint32_t a0, uint32_t a1,
                                        uint32_t a2, uint32_t a3,
                                        uint32_t b0, uint32_t b1) {
    asm volatile("mma.sync.aligned.m16n8k16.row.col.f32.f16.f16.f32 "
                 "{%0,%1,%2,%3}, {%4,%5,%6,%7}, {%8,%9}, {%0,%1,%2,%3};"
                 : "+f"(c[0]), "+f"(c[1]), "+f"(c[2]), "+f"(c[3])
                 : "r"(a0), "r"(a1), "r"(a2), "r"(a3), "r"(b0), "r"(b1));
}
__device__ __forceinline__ void cp16(uint32_t dst, const void* src) {
    asm volatile("cp.async.cg.shared.global [%0], [%1], 16;\n" :: "r"(dst), "l"(src));
}
__device__ __forceinline__ void cp_commit() { asm volatile("cp.async.commit_group;\n"); }
template<int N> __device__ __forceinline__ void cp_wait() {
    asm volatile("cp.async.wait_group %0;\n" :: "n"(N));
}

__global__ void __launch_bounds__(256, 1) transform_k(
    const float* __restrict__ W, const float* __restrict__ Wroot,
    const float* __restrict__ b, const float* __restrict__ hin,
    const __half* __restrict__ hh,
    float* __restrict__ out, __half* __restrict__ outh) {
    extern __shared__ __align__(16) uint32_t sm[];
    uint32_t* sWt = sm;                   // [64][WPITCH] half2 pairs, transposed
    uint32_t* sA  = sm + 64*WPITCH;       // NSTG stages x [128][APITCH] words
    const int tid  = threadIdx.x;
    const int lane = tid & 31;
    const int wid  = tid >> 5;
    const int g    = lane >> 2;
    const int tig  = lane & 3;
    const int wm   = wid & 3;
    const int wn   = wid >> 2;

    // Wt[n][kw] = half2(W[2kw][n], W[2kw+1][n]); Wroot at k>=512
    for (int idx = tid; idx < 64*(KTOT/2); idx += 256) {
        int n = idx / (KTOT/2), kw = idx % (KTOT/2);
        int k0 = kw*2;
        float v0 = (k0   < KS) ? W[(size_t)k0*Dd + n]     : Wroot[(size_t)(k0-KS)*Dd + n];
        float v1 = (k0+1 < KS) ? W[(size_t)(k0+1)*Dd + n] : Wroot[(size_t)(k0+1-KS)*Dd + n];
        sWt[n*WPITCH + kw] = h2_bits(__floats2half2_rn(v0, v1));
    }
    __syncthreads();

    const uint32_t sA_u32 = (uint32_t)__cvta_generic_to_shared(sA);

    for (int tile = blockIdx.x; tile < NTILES; tile += gridDim.x) {
        const int node0 = tile * TILE;

        // issue one 64-half K-chunk (16KB) into stage kc%NSTG; 4 x cp16/thread
        auto issue = [&](int kc) {
            const int stage = kc & (NSTG - 1);
            #pragma unroll
            for (int u = 0; u < 4; u++) {
                int idx  = tid + u*256;          // 0..1023
                int nd   = idx >> 3;             // node within tile
                int part = idx & 7;              // 16B unit within 128B row
                int n    = node0 + nd;
                int nc   = (n < Nn) ? n : (Nn - 1);
                const void* src = (kc < 8)
                    ? (const void*)(g_Sh + (size_t)nc*KS + kc*KC + part*8)
                    : (const void*)(hh   + (size_t)nc*Dd + part*8);
                cp16(sA_u32 + (uint32_t)(((stage*TILE + nd)*APITCH + part*4) * 4), src);
            }
            cp_commit();
        };

        float acc[2][4][4];
        #pragma unroll
        for (int mf = 0; mf < 2; mf++)
            #pragma unroll
            for (int nf = 0; nf < 4; nf++)
                { acc[mf][nf][0]=0.f; acc[mf][nf][1]=0.f; acc[mf][nf][2]=0.f; acc[mf][nf][3]=0.f; }

        issue(0); issue(1); issue(2);
        for (int kc = 0; kc < NCHK; kc++) {
            cp_wait<2>();
            __syncthreads();
            const uint32_t* aS = sA + (kc & (NSTG - 1))*TILE*APITCH;
            #pragma unroll
            for (int ks = 0; ks < 4; ks++) {               // 4 x k16 steps
                const int klw = ks*8;                      // local kword base
                const int kgw = kc*32 + klw;               // global kword base
                uint32_t bf[4][2];
                #pragma unroll
                for (int nf = 0; nf < 4; nf++) {
                    const uint32_t* bp = sWt + (wn*32 + nf*8 + g)*WPITCH + kgw + tig;
                    bf[nf][0] = bp[0]; bf[nf][1] = bp[4];
                }
                #pragma unroll
                for (int mf = 0; mf < 2; mf++) {
                    const uint32_t* ap = aS + (wm*32 + mf*16)*APITCH + klw;
                    uint32_t a0 = ap[ g     *APITCH + tig    ];
                    uint32_t a1 = ap[(g + 8)*APITCH + tig    ];
                    uint32_t a2 = ap[ g     *APITCH + tig + 4];
                    uint32_t a3 = ap[(g + 8)*APITCH + tig + 4];
                    #pragma unroll
                    for (int nf = 0; nf < 4; nf++)
                        mma_f16(acc[mf][nf], a0, a1, a2, a3, bf[nf][0], bf[nf][1]);
                }
            }
            __syncthreads();
            if (kc + 3 < NCHK) issue(kc + 3);
            else               cp_commit();
        }

        // epilogue: out = h + relu(acc + bias); also fp16 mirror for next layer
        #pragma unroll
        for (int mf = 0; mf < 2; mf++) {
            #pragma unroll
            for (int nf = 0; nf < 4; nf++) {
                int col = wn*32 + nf*8 + tig*2;
                float2 bv = *(const float2*)(b + col);
                #pragma unroll
                for (int half = 0; half < 2; half++) {
                    int r = node0 + wm*32 + mf*16 + g + half*8;
                    if (r < Nn) {
                        float2 hv = *(const float2*)(hin + (size_t)r*Dd + col);
                        float2 o;
                        o.x = hv.x + fmaxf(acc[mf][nf][half*2 + 0] + bv.x, 0.f);
                        o.y = hv.y + fmaxf(acc[mf][nf][half*2 + 1] + bv.y, 0.f);
                        *(float2*)(out + (size_t)r*Dd + col) = o;
                        ((__half2*)(outh + (size_t)r*Dd))[col >> 1] =
                            __floats2half2_rn(o.x, o.y);
                    }
                }
            }
        }
    }
}

// ---------------------------------------------------------------------------
extern "C" void kernel_launch(void* const* d_in, const int* in_sizes, int n_in,
                              void* d_out, int out_size) {
    const int*   x     = (const int*)d_in[0];
    const int*   eidx  = (const int*)d_in[1];
    const int*   et    = (const int*)d_in[2];
    const int*   ntype = (const int*)d_in[3];
    const float* props = (const float*)d_in[4];
    const float* nemb  = (const float*)d_in[5];
    const float* temb  = (const float*)d_in[6];
    const float* pw1   = (const float*)d_in[7];
    const float* pb1   = (const float*)d_in[8];
    const float* pw2   = (const float*)d_in[9];
    const float* pb2   = (const float*)d_in[10];
    const float* W1    = (const float*)d_in[11];
    const float* Wr1   = (const float*)d_in[12];
    const float* b1    = (const float*)d_in[13];
    const float* W2    = (const float*)d_in[14];
    const float* Wr2   = (const float*)d_in[15];
    const float* b2    = (const float*)d_in[16];
    float* out = (float*)d_out;
    const int* src = eidx;
    const int* dst = eidx + Ee;

    void *ph, *ph2, *phh, *phh2;
    cudaGetSymbolAddress(&ph,   g_h);
    cudaGetSymbolAddress(&ph2,  g_h2);
    cudaGetSymbolAddress(&phh,  g_hh);
    cudaGetSymbolAddress(&phh2, g_hh2);
    float*  h   = (float*)ph;
    float*  h2  = (float*)ph2;
    __half* hh  = (__half*)phh;
    __half* hh2 = (__half*)phh2;

    size_t smem = (size_t)(64*WPITCH + NSTG*TILE*APITCH) * 4;   // 148480 B
    cudaFuncSetAttribute(transform_k, cudaFuncAttributeMaxDynamicSharedMemorySize, (int)smem);

    // ---- CSR build ----
    zero_k<<<(NR+255)/256, 256>>>();
    count_k<<<(Ee+255)/256, 256>>>(dst, et);
    scan1_k<<<SCAN_BLKS, 256>>>();
    scan2_k<<<1, 256>>>();
    scan3_k<<<(NR+255)/256, 256>>>();
    fill_k<<<(Ee+255)/256, 256>>>(src, dst, et);
    mlp_k<<<1536, 256>>>(x, ntype, props, nemb, temb, pw1, pb1, pw2, pb2);

    // layer 1
    seg_sum_k<<<3200, 256>>>(h);
    transform_k<<<148, 256, smem>>>(W1, Wr1, b1, h, hh, h2, hh2);

    // layer 2
    seg_sum_k<<<3200, 256>>>(h2);
    transform_k<<<148, 256, smem>>>(W2, Wr2, b2, h2, hh2, out, hh);
}